// round 4
// baseline (speedup 1.0000x reference)
#include <cuda_runtime.h>
#include <cuda_bf16.h>
#include <math_constants.h>

// Problem constants (fixed by the dataset)
#define N_NODES   20000
#define N_EDGES   320000
#define HID       128
#define NRAD      16
#define CUTOFF_F  5.0f
#define D0        0.5f
#define D1        5.0f

// LUT: f(d)=silu(rbf@W_rbf0+b0)@W2 + b_lin  and  g(d)=rbf@W_rbf1, lerp over d∈[0.5,5].
// Max |f''| ~ (16π/5)^2 × amplitude → lerp error ≈ h²/8·|f''| ≈ 1.5e-5 ≪ 1e-3 budget.
#define LUT_N     4096
#define LUT_STEP  ((D1 - D0) / (float)(LUT_N - 1))
#define LUT_INV   ((float)(LUT_N - 1) / (D1 - D0))

// Scratch (__device__ globals: allocation-free per harness rules)
__device__ float g_Z[N_NODES * 256];      // [node][0:128]=W0-proj, [128:256]=W1-proj (20.5 MB, L2-resident)
__device__ float g_LUT[LUT_N * 256];      // [row][0:128]=f(d)+b_lin, [128:256]=g(d)  (4.2 MB, L2-resident)

// ---------------------------------------------------------------------------
// Kernel 1: Z = node_embs @ [W0 | W1]   (M=20000, N=256, K=128)
// Register-tiled SGEMM: BM=BN=128, BK=16, 256 threads, 8x8 microtile.
// ---------------------------------------------------------------------------
__global__ __launch_bounds__(256) void z_gemm_kernel(
    const float* __restrict__ A,       // node_embs [20000,128]
    const float* __restrict__ W_lin)   // [384,128] row-major
{
    __shared__ float As[16][132];      // 132-float row pitch: float4-aligned, conflict-free
    __shared__ float Bs[16][128];

    const int m0   = blockIdx.x * 128;
    const int nblk = blockIdx.y;                 // 0 -> W0 rows 0..127, 1 -> W1 rows 128..255
    const float* B = W_lin + nblk * 128 * 128;

    const int tid = threadIdx.x;
    const int tx  = tid & 15;
    const int ty  = tid >> 4;

    float acc[8][8];
    #pragma unroll
    for (int i = 0; i < 8; i++)
        #pragma unroll
        for (int j = 0; j < 8; j++) acc[i][j] = 0.0f;

    for (int k0 = 0; k0 < 128; k0 += 16) {
        #pragma unroll
        for (int i = 0; i < 2; i++) {
            int idx = tid + i * 256;        // 512 float4 slots
            int row = idx >> 2;             // 0..127
            int kq  = (idx & 3) * 4;        // 0,4,8,12
            int gm  = m0 + row;
            float4 v = make_float4(0.f, 0.f, 0.f, 0.f);
            if (gm < N_NODES) v = *(const float4*)(A + (size_t)gm * 128 + k0 + kq);
            As[kq + 0][row] = v.x;
            As[kq + 1][row] = v.y;
            As[kq + 2][row] = v.z;
            As[kq + 3][row] = v.w;
        }
        #pragma unroll
        for (int i = 0; i < 2; i++) {
            int idx = tid + i * 256;
            int k   = idx >> 5;             // 0..15
            int nq  = (idx & 31) * 4;
            *(float4*)&Bs[k][nq] = *(const float4*)(B + (size_t)(k0 + k) * 128 + nq);
        }
        __syncthreads();

        #pragma unroll
        for (int k = 0; k < 16; k++) {
            float a[8], b[8];
            float4 a0 = *(const float4*)&As[k][ty * 8];
            float4 a1 = *(const float4*)&As[k][ty * 8 + 4];
            float4 b0 = *(const float4*)&Bs[k][tx * 8];
            float4 b1 = *(const float4*)&Bs[k][tx * 8 + 4];
            a[0]=a0.x; a[1]=a0.y; a[2]=a0.z; a[3]=a0.w; a[4]=a1.x; a[5]=a1.y; a[6]=a1.z; a[7]=a1.w;
            b[0]=b0.x; b[1]=b0.y; b[2]=b0.z; b[3]=b0.w; b[4]=b1.x; b[5]=b1.y; b[6]=b1.z; b[7]=b1.w;
            #pragma unroll
            for (int i = 0; i < 8; i++)
                #pragma unroll
                for (int j = 0; j < 8; j++)
                    acc[i][j] = fmaf(a[i], b[j], acc[i][j]);
        }
        __syncthreads();
    }

    #pragma unroll
    for (int i = 0; i < 8; i++) {
        int gm = m0 + ty * 8 + i;
        if (gm < N_NODES) {
            float* dst = g_Z + (size_t)gm * 256 + nblk * 128 + tx * 8;
            *(float4*)(dst)     = make_float4(acc[i][0], acc[i][1], acc[i][2], acc[i][3]);
            *(float4*)(dst + 4) = make_float4(acc[i][4], acc[i][5], acc[i][6], acc[i][7]);
        }
    }
}

// ---------------------------------------------------------------------------
// Kernel 2: LUT build. Block = 8 LUT rows; 128 threads = hidden dim.
// f = silu(rbf@W_rbf0 + b0) @ W_lin[256:384,:] + b_lin,   g = rbf @ W_rbf1
// ---------------------------------------------------------------------------
__global__ __launch_bounds__(128) void lut_kernel(
    const float* __restrict__ W_rbf0,  // [16,128]
    const float* __restrict__ b_rbf0,  // [128]
    const float* __restrict__ W_lin,   // [384,128]
    const float* __restrict__ b_lin,   // [128]
    const float* __restrict__ W_rbf1)  // [16,128]
{
    __shared__ float rbf_s[8][NRAD];
    __shared__ float a_s[8][HID];

    const int h  = threadIdx.x;            // 0..127
    const int r0 = blockIdx.x * 8;

    {
        int row = h >> 4;
        int n   = (h & 15) + 1;
        float d = D0 + (float)(r0 + row) * LUT_STEP;
        const float norm = 0.6324555320336759f;        // sqrt(2/5)
        float freq = (float)n * (CUDART_PI_F / CUTOFF_F);
        rbf_s[row][n - 1] = norm * sinf(d * freq) / d;  // full-precision (one-time)
    }
    __syncthreads();

    float y[8];
    float b0 = b_rbf0[h];
    #pragma unroll
    for (int row = 0; row < 8; row++) y[row] = b0;
    #pragma unroll
    for (int r = 0; r < NRAD; r++) {
        float w = W_rbf0[r * HID + h];
        #pragma unroll
        for (int row = 0; row < 8; row++)
            y[row] = fmaf(rbf_s[row][r], w, y[row]);
    }
    #pragma unroll
    for (int row = 0; row < 8; row++) {
        float v = y[row];
        a_s[row][h] = v / (1.0f + expf(-v));           // accurate silu (one-time)
    }
    __syncthreads();

    float f[8];
    float bl = b_lin[h];                               // fold bias into LUT
    #pragma unroll
    for (int row = 0; row < 8; row++) f[row] = bl;
    for (int k = 0; k < HID; k++) {
        float w2 = W_lin[(size_t)(256 + k) * HID + h]; // W2 = rows 256..383
        #pragma unroll
        for (int row = 0; row < 8; row++)
            f[row] = fmaf(a_s[row][k], w2, f[row]);
    }

    float g[8];
    #pragma unroll
    for (int row = 0; row < 8; row++) g[row] = 0.0f;
    #pragma unroll
    for (int r = 0; r < NRAD; r++) {
        float w = W_rbf1[r * HID + h];
        #pragma unroll
        for (int row = 0; row < 8; row++)
            g[row] = fmaf(rbf_s[row][r], w, g[row]);
    }

    #pragma unroll
    for (int row = 0; row < 8; row++) {
        g_LUT[(size_t)(r0 + row) * 256 + h]       = f[row];
        g_LUT[(size_t)(r0 + row) * 256 + 128 + h] = g[row];
    }
}

// ---------------------------------------------------------------------------
// Kernel 3: edge kernel. Warp per edge, lane = 4 hidden units (float4).
//   e1 = silu(Z[src][0:128] + Z[dst][128:256] + lerp_f(d))   (b_lin pre-folded)
//   e2 = lerp_g(d) * e1
// ---------------------------------------------------------------------------
__global__ __launch_bounds__(256) void edge_kernel(
    const int*   __restrict__ ei,      // [2, E]
    const float* __restrict__ ew,      // [E]
    float*       __restrict__ out)     // [2*E*128]: e1 then e2
{
    const int warp = (blockIdx.x * blockDim.x + threadIdx.x) >> 5;
    const int lane = threadIdx.x & 31;
    if (warp >= N_EDGES) return;
    const int e = warp;

    const float d = __ldg(ew + e);
    const int   s = __ldg(ei + e);
    const int   t = __ldg(ei + N_EDGES + e);

    float tp = (d - D0) * LUT_INV;
    tp = fminf(fmaxf(tp, 0.0f), (float)(LUT_N - 1) - 1e-3f);  // clamp BEFORE cast (NaN/range safe)
    int i0 = (int)tp;
    if (i0 > LUT_N - 2) i0 = LUT_N - 2;
    const float tw = tp - (float)i0;

    const float4* L0 = (const float4*)(g_LUT + (size_t)i0 * 256);
    const float4 f0 = __ldg(L0 + lane);
    const float4 g0 = __ldg(L0 + 32 + lane);
    const float4 f1 = __ldg(L0 + 64 + lane);       // next LUT row, f part
    const float4 g1 = __ldg(L0 + 96 + lane);       // next LUT row, g part

    const float4 zs = __ldg((const float4*)(g_Z + (size_t)s * 256) + lane);
    const float4 zd = __ldg((const float4*)(g_Z + (size_t)t * 256 + 128) + lane);

    float4 e1v, e2v;
    #define COMP(c)                                                    \
    {                                                                  \
        float fi  = fmaf(tw, f1.c - f0.c, f0.c);                       \
        float gi  = fmaf(tw, g1.c - g0.c, g0.c);                       \
        float pre = zs.c + zd.c + fi;                                  \
        float sv  = __fdividef(pre, 1.0f + __expf(-pre));              \
        e1v.c = sv;                                                    \
        e2v.c = gi * sv;                                               \
    }
    COMP(x) COMP(y) COMP(z) COMP(w)
    #undef COMP

    *((float4*)(out + (size_t)e * HID) + lane) = e1v;
    *((float4*)(out + (size_t)N_EDGES * HID + (size_t)e * HID) + lane) = e2v;
}

// ---------------------------------------------------------------------------
extern "C" void kernel_launch(void* const* d_in, const int* in_sizes, int n_in,
                              void* d_out, int out_size)
{
    const float* node_embs = (const float*)d_in[0];
    const int*   edge_idx  = (const int*)  d_in[1];
    const float* edge_w    = (const float*)d_in[2];
    const float* W_rbf0    = (const float*)d_in[3];
    const float* b_rbf0    = (const float*)d_in[4];
    const float* W_lin     = (const float*)d_in[5];
    const float* b_lin     = (const float*)d_in[6];
    const float* W_rbf1    = (const float*)d_in[7];
    float* out = (float*)d_out;

    // 1) Z = node_embs @ [W0|W1]
    {
        dim3 grid((N_NODES + 127) / 128, 2);
        z_gemm_kernel<<<grid, 256>>>(node_embs, W_lin);
    }
    // 2) d-dependent LUT (b_lin folded into f)
    lut_kernel<<<LUT_N / 8, 128>>>(W_rbf0, b_rbf0, W_lin, b_lin, W_rbf1);
    // 3) per-edge fuse: warp per edge, 8 warps per block
    edge_kernel<<<(N_EDGES + 7) / 8, 256>>>(edge_idx, edge_w, out);

    (void)in_sizes; (void)n_in; (void)out_size;
}

// round 14
// speedup vs baseline: 1.1494x; 1.1494x over previous
#include <cuda_runtime.h>
#include <cuda_fp16.h>
#include <math_constants.h>

// Problem constants (fixed by the dataset)
#define N_NODES   20000
#define N_EDGES   320000
#define HID       128
#define NRAD      16
#define CUTOFF_F  5.0f
#define D0        0.5f
#define D1        5.0f

// LUT: f(d)=silu(rbf@W_rbf0+b0)@W2 + b_lin  and  g(d)=rbf@W_rbf1, lerp over d∈[0.5,5].
#define LUT_N     4096
#define LUT_STEP  ((D1 - D0) / (float)(LUT_N - 1))
#define LUT_INV   ((float)(LUT_N - 1) / (D1 - D0))

// fp16 scratch: halves the L2-read bytes of the (L2-roofline-bound) edge kernel.
__device__ __half g_Zh[N_NODES * 256];    // [node][0:128]=W0-proj, [128:256]=W1-proj (10.2 MB)
__device__ __half g_LUTh[LUT_N * 256];    // [row][0:128]=f(d)+b_lin, [128:256]=g(d)  (2.1 MB)

// ---------------------------------------------------------------------------
// Kernel 1: Z = node_embs @ [W0 | W1]   (M=20000, N=256, K=128), fp16 output.
// BM=96, BN=128, BK=16, 256 threads, 6x8 microtile, 3 blocks/SM forced.
// grid = 209*2 = 418 <= 148*3 = 444 concurrent slots -> SINGLE WAVE
// (fixes the measured 1.06-wave quantization that cost ~45% of the old 59.9us).
// ---------------------------------------------------------------------------
__global__ __launch_bounds__(256, 3) void z_gemm_kernel(
    const float* __restrict__ A,       // node_embs [20000,128]
    const float* __restrict__ W_lin)   // [384,128] row-major
{
    __shared__ float As[16][100];      // 96 + pad
    __shared__ float Bs[16][128];

    const int m0   = blockIdx.x * 96;
    const int nblk = blockIdx.y;                 // 0 -> W0 rows 0..127, 1 -> W1 rows 128..255
    const float* B = W_lin + nblk * 128 * 128;

    const int tid = threadIdx.x;
    const int tx  = tid & 15;     // 16 col-groups of 8
    const int ty  = tid >> 4;     // 16 row-groups of 6

    float acc[6][8];
    #pragma unroll
    for (int i = 0; i < 6; i++)
        #pragma unroll
        for (int j = 0; j < 8; j++) acc[i][j] = 0.0f;

    for (int k0 = 0; k0 < 128; k0 += 16) {
        // A tile: 96 rows x 16 k = 384 float4 slots
        for (int idx = tid; idx < 384; idx += 256) {
            int row = idx >> 2;             // 0..95
            int kq  = (idx & 3) * 4;        // 0,4,8,12
            int gm  = m0 + row;
            float4 v = make_float4(0.f, 0.f, 0.f, 0.f);
            if (gm < N_NODES) v = *(const float4*)(A + (size_t)gm * 128 + k0 + kq);
            As[kq + 0][row] = v.x;
            As[kq + 1][row] = v.y;
            As[kq + 2][row] = v.z;
            As[kq + 3][row] = v.w;
        }
        // B tile: 16 k x 128 n = 512 float4 slots
        #pragma unroll
        for (int i = 0; i < 2; i++) {
            int idx = tid + i * 256;
            int k   = idx >> 5;             // 0..15
            int nq  = (idx & 31) * 4;
            *(float4*)&Bs[k][nq] = *(const float4*)(B + (size_t)(k0 + k) * 128 + nq);
        }
        __syncthreads();

        #pragma unroll
        for (int k = 0; k < 16; k++) {
            float a[6];
            #pragma unroll
            for (int i = 0; i < 6; i++) a[i] = As[k][ty * 6 + i];
            float4 b0 = *(const float4*)&Bs[k][tx * 8];
            float4 b1 = *(const float4*)&Bs[k][tx * 8 + 4];
            float b[8];
            b[0]=b0.x; b[1]=b0.y; b[2]=b0.z; b[3]=b0.w;
            b[4]=b1.x; b[5]=b1.y; b[6]=b1.z; b[7]=b1.w;
            #pragma unroll
            for (int i = 0; i < 6; i++)
                #pragma unroll
                for (int j = 0; j < 8; j++)
                    acc[i][j] = fmaf(a[i], b[j], acc[i][j]);
        }
        __syncthreads();
    }

    // Store fp16: 8 halfs (16B) per row-fragment
    #pragma unroll
    for (int i = 0; i < 6; i++) {
        int gm = m0 + ty * 6 + i;
        if (gm < N_NODES) {
            __half* dst = g_Zh + (size_t)gm * 256 + nblk * 128 + tx * 8;
            __half2 h0 = __floats2half2_rn(acc[i][0], acc[i][1]);
            __half2 h1 = __floats2half2_rn(acc[i][2], acc[i][3]);
            __half2 h2 = __floats2half2_rn(acc[i][4], acc[i][5]);
            __half2 h3 = __floats2half2_rn(acc[i][6], acc[i][7]);
            uint4 pk;
            pk.x = *(unsigned int*)&h0;
            pk.y = *(unsigned int*)&h1;
            pk.z = *(unsigned int*)&h2;
            pk.w = *(unsigned int*)&h3;
            *(uint4*)dst = pk;
        }
    }
}

// ---------------------------------------------------------------------------
// Kernel 2: LUT build (fp16 output). Block = 8 LUT rows; 128 threads = hidden dim.
// f = silu(rbf@W_rbf0 + b0) @ W_lin[256:384,:] + b_lin,   g = rbf @ W_rbf1
// ---------------------------------------------------------------------------
__global__ __launch_bounds__(128) void lut_kernel(
    const float* __restrict__ W_rbf0,  // [16,128]
    const float* __restrict__ b_rbf0,  // [128]
    const float* __restrict__ W_lin,   // [384,128]
    const float* __restrict__ b_lin,   // [128]
    const float* __restrict__ W_rbf1)  // [16,128]
{
    __shared__ float rbf_s[8][NRAD];
    __shared__ float a_s[8][HID];

    const int h  = threadIdx.x;            // 0..127
    const int r0 = blockIdx.x * 8;

    {
        int row = h >> 4;
        int n   = (h & 15) + 1;
        float d = D0 + (float)(r0 + row) * LUT_STEP;
        const float norm = 0.6324555320336759f;        // sqrt(2/5)
        float freq = (float)n * (CUDART_PI_F / CUTOFF_F);
        rbf_s[row][n - 1] = norm * sinf(d * freq) / d;  // full precision (one-time)
    }
    __syncthreads();

    float y[8];
    float b0 = b_rbf0[h];
    #pragma unroll
    for (int row = 0; row < 8; row++) y[row] = b0;
    #pragma unroll
    for (int r = 0; r < NRAD; r++) {
        float w = W_rbf0[r * HID + h];
        #pragma unroll
        for (int row = 0; row < 8; row++)
            y[row] = fmaf(rbf_s[row][r], w, y[row]);
    }
    #pragma unroll
    for (int row = 0; row < 8; row++) {
        float v = y[row];
        a_s[row][h] = v / (1.0f + expf(-v));           // accurate silu (one-time)
    }
    __syncthreads();

    float f[8];
    float bl = b_lin[h];                               // fold bias into LUT
    #pragma unroll
    for (int row = 0; row < 8; row++) f[row] = bl;
    for (int k = 0; k < HID; k++) {
        float w2 = W_lin[(size_t)(256 + k) * HID + h]; // W2 = rows 256..383
        #pragma unroll
        for (int row = 0; row < 8; row++)
            f[row] = fmaf(a_s[row][k], w2, f[row]);
    }

    float g[8];
    #pragma unroll
    for (int row = 0; row < 8; row++) g[row] = 0.0f;
    #pragma unroll
    for (int r = 0; r < NRAD; r++) {
        float w = W_rbf1[r * HID + h];
        #pragma unroll
        for (int row = 0; row < 8; row++)
            g[row] = fmaf(rbf_s[row][r], w, g[row]);
    }

    #pragma unroll
    for (int row = 0; row < 8; row++) {
        g_LUTh[(size_t)(r0 + row) * 256 + h]       = __float2half_rn(f[row]);
        g_LUTh[(size_t)(r0 + row) * 256 + 128 + h] = __float2half_rn(g[row]);
    }
}

// ---------------------------------------------------------------------------
// Kernel 3: edge kernel (L2-roofline-bound; fp16 halves the read bytes).
// Warp per edge, lane = 4 hidden units (8B fp16 loads, fp32 math + output).
//   e1 = silu(Z[src][0:128] + Z[dst][128:256] + lerp_f(d))   (b_lin pre-folded)
//   e2 = lerp_g(d) * e1
// ---------------------------------------------------------------------------
__device__ __forceinline__ float4 h4_to_f4(uint2 v) {
    __half2 lo = *reinterpret_cast<__half2*>(&v.x);
    __half2 hi = *reinterpret_cast<__half2*>(&v.y);
    float2 a = __half22float2(lo);
    float2 b = __half22float2(hi);
    return make_float4(a.x, a.y, b.x, b.y);
}

__global__ __launch_bounds__(256) void edge_kernel(
    const int*   __restrict__ ei,      // [2, E]
    const float* __restrict__ ew,      // [E]
    float*       __restrict__ out)     // [2*E*128]: e1 then e2
{
    const int warp = (blockIdx.x * blockDim.x + threadIdx.x) >> 5;
    const int lane = threadIdx.x & 31;
    if (warp >= N_EDGES) return;
    const int e = warp;

    const float d = __ldg(ew + e);
    const int   s = __ldg(ei + e);
    const int   t = __ldg(ei + N_EDGES + e);

    float tp = (d - D0) * LUT_INV;
    tp = fminf(fmaxf(tp, 0.0f), (float)(LUT_N - 1) - 1e-3f);  // clamp BEFORE cast
    int i0 = (int)tp;
    if (i0 > LUT_N - 2) i0 = LUT_N - 2;
    const float tw = tp - (float)i0;

    // LUT row = 256 halfs = 64 uint2; lane -> 4 hidden units (one uint2)
    const uint2* L0 = (const uint2*)(g_LUTh + (size_t)i0 * 256);
    const float4 f0 = h4_to_f4(__ldg(L0 + lane));
    const float4 g0 = h4_to_f4(__ldg(L0 + 32 + lane));
    const float4 f1 = h4_to_f4(__ldg(L0 + 64 + lane));   // next row, f part
    const float4 g1 = h4_to_f4(__ldg(L0 + 96 + lane));   // next row, g part

    const float4 zs = h4_to_f4(__ldg((const uint2*)(g_Zh + (size_t)s * 256) + lane));
    const float4 zd = h4_to_f4(__ldg((const uint2*)(g_Zh + (size_t)t * 256 + 128) + lane));

    float4 e1v, e2v;
    #define COMP(c)                                                    \
    {                                                                  \
        float fi  = fmaf(tw, f1.c - f0.c, f0.c);                       \
        float gi  = fmaf(tw, g1.c - g0.c, g0.c);                       \
        float pre = zs.c + zd.c + fi;                                  \
        float sv  = __fdividef(pre, 1.0f + __expf(-pre));              \
        e1v.c = sv;                                                    \
        e2v.c = gi * sv;                                               \
    }
    COMP(x) COMP(y) COMP(z) COMP(w)
    #undef COMP

    *((float4*)(out + (size_t)e * HID) + lane) = e1v;
    *((float4*)(out + (size_t)N_EDGES * HID + (size_t)e * HID) + lane) = e2v;
}

// ---------------------------------------------------------------------------
extern "C" void kernel_launch(void* const* d_in, const int* in_sizes, int n_in,
                              void* d_out, int out_size)
{
    const float* node_embs = (const float*)d_in[0];
    const int*   edge_idx  = (const int*)  d_in[1];
    const float* edge_w    = (const float*)d_in[2];
    const float* W_rbf0    = (const float*)d_in[3];
    const float* b_rbf0    = (const float*)d_in[4];
    const float* W_lin     = (const float*)d_in[5];
    const float* b_lin     = (const float*)d_in[6];
    const float* W_rbf1    = (const float*)d_in[7];
    float* out = (float*)d_out;

    // 1) Z = node_embs @ [W0|W1], fp16 out. grid 209x2=418 <= 444 slots: single wave.
    {
        dim3 grid((N_NODES + 95) / 96, 2);
        z_gemm_kernel<<<grid, 256>>>(node_embs, W_lin);
    }
    // 2) d-dependent LUT (b_lin folded into f), fp16 out
    lut_kernel<<<LUT_N / 8, 128>>>(W_rbf0, b_rbf0, W_lin, b_lin, W_rbf1);
    // 3) per-edge fuse: warp per edge, 8 warps per block
    edge_kernel<<<(N_EDGES + 7) / 8, 256>>>(edge_idx, edge_w, out);

    (void)in_sizes; (void)n_in; (void)out_size;
}

// round 15
// speedup vs baseline: 1.4287x; 1.2430x over previous
#include <cuda_runtime.h>
#include <cuda_fp16.h>
#include <math_constants.h>

// Problem constants (fixed by the dataset)
#define N_NODES   20000
#define N_EDGES   320000
#define HID       128
#define NRAD      16
#define CUTOFF_F  5.0f
#define D0        0.5f
#define D1        5.0f

// LUT: f(d)=silu(rbf@W_rbf0+b0)@W2 + b_lin  and  g(d)=rbf@W_rbf1, lerp over d∈[0.5,5].
#define LUT_N     4096
#define LUT_STEP  ((D1 - D0) / (float)(LUT_N - 1))
#define LUT_INV   ((float)(LUT_N - 1) / (D1 - D0))

// fp16 scratch (validated: rel_err 2.8e-4 vs 1e-3 gate)
__device__ __half g_Zh[N_NODES * 256];    // [node][0:128]=W0-proj, [128:256]=W1-proj (10.2 MB)
__device__ __half g_LUTh[LUT_N * 256];    // [row][0:128]=f(d)+b_lin, [128:256]=g(d)  (2.1 MB)

// ---------------------------------------------------------------------------
// Kernel 1: Z = node_embs @ [W0 | W1]  (measured 40.7us, single wave, occ 33%)
// UNCHANGED this round — edge kernel is the target.
// ---------------------------------------------------------------------------
__global__ __launch_bounds__(256, 3) void z_gemm_kernel(
    const float* __restrict__ A,       // node_embs [20000,128]
    const float* __restrict__ W_lin)   // [384,128] row-major
{
    __shared__ float As[16][100];      // 96 + pad
    __shared__ float Bs[16][128];

    const int m0   = blockIdx.x * 96;
    const int nblk = blockIdx.y;                 // 0 -> W0 rows 0..127, 1 -> W1 rows 128..255
    const float* B = W_lin + nblk * 128 * 128;

    const int tid = threadIdx.x;
    const int tx  = tid & 15;     // 16 col-groups of 8
    const int ty  = tid >> 4;     // 16 row-groups of 6

    float acc[6][8];
    #pragma unroll
    for (int i = 0; i < 6; i++)
        #pragma unroll
        for (int j = 0; j < 8; j++) acc[i][j] = 0.0f;

    for (int k0 = 0; k0 < 128; k0 += 16) {
        // A tile: 96 rows x 16 k = 384 float4 slots
        for (int idx = tid; idx < 384; idx += 256) {
            int row = idx >> 2;             // 0..95
            int kq  = (idx & 3) * 4;        // 0,4,8,12
            int gm  = m0 + row;
            float4 v = make_float4(0.f, 0.f, 0.f, 0.f);
            if (gm < N_NODES) v = *(const float4*)(A + (size_t)gm * 128 + k0 + kq);
            As[kq + 0][row] = v.x;
            As[kq + 1][row] = v.y;
            As[kq + 2][row] = v.z;
            As[kq + 3][row] = v.w;
        }
        // B tile: 16 k x 128 n = 512 float4 slots
        #pragma unroll
        for (int i = 0; i < 2; i++) {
            int idx = tid + i * 256;
            int k   = idx >> 5;             // 0..15
            int nq  = (idx & 31) * 4;
            *(float4*)&Bs[k][nq] = *(const float4*)(B + (size_t)(k0 + k) * 128 + nq);
        }
        __syncthreads();

        #pragma unroll
        for (int k = 0; k < 16; k++) {
            float a[6];
            #pragma unroll
            for (int i = 0; i < 6; i++) a[i] = As[k][ty * 6 + i];
            float4 b0 = *(const float4*)&Bs[k][tx * 8];
            float4 b1 = *(const float4*)&Bs[k][tx * 8 + 4];
            float b[8];
            b[0]=b0.x; b[1]=b0.y; b[2]=b0.z; b[3]=b0.w;
            b[4]=b1.x; b[5]=b1.y; b[6]=b1.z; b[7]=b1.w;
            #pragma unroll
            for (int i = 0; i < 6; i++)
                #pragma unroll
                for (int j = 0; j < 8; j++)
                    acc[i][j] = fmaf(a[i], b[j], acc[i][j]);
        }
        __syncthreads();
    }

    // Store fp16: 8 halfs (16B) per row-fragment
    #pragma unroll
    for (int i = 0; i < 6; i++) {
        int gm = m0 + ty * 6 + i;
        if (gm < N_NODES) {
            __half* dst = g_Zh + (size_t)gm * 256 + nblk * 128 + tx * 8;
            __half2 h0 = __floats2half2_rn(acc[i][0], acc[i][1]);
            __half2 h1 = __floats2half2_rn(acc[i][2], acc[i][3]);
            __half2 h2 = __floats2half2_rn(acc[i][4], acc[i][5]);
            __half2 h3 = __floats2half2_rn(acc[i][6], acc[i][7]);
            uint4 pk;
            pk.x = *(unsigned int*)&h0;
            pk.y = *(unsigned int*)&h1;
            pk.z = *(unsigned int*)&h2;
            pk.w = *(unsigned int*)&h3;
            *(uint4*)dst = pk;
        }
    }
}

// ---------------------------------------------------------------------------
// Kernel 2: LUT build (fp16 output). UNCHANGED.
// ---------------------------------------------------------------------------
__global__ __launch_bounds__(128) void lut_kernel(
    const float* __restrict__ W_rbf0,  // [16,128]
    const float* __restrict__ b_rbf0,  // [128]
    const float* __restrict__ W_lin,   // [384,128]
    const float* __restrict__ b_lin,   // [128]
    const float* __restrict__ W_rbf1)  // [16,128]
{
    __shared__ float rbf_s[8][NRAD];
    __shared__ float a_s[8][HID];

    const int h  = threadIdx.x;            // 0..127
    const int r0 = blockIdx.x * 8;

    {
        int row = h >> 4;
        int n   = (h & 15) + 1;
        float d = D0 + (float)(r0 + row) * LUT_STEP;
        const float norm = 0.6324555320336759f;        // sqrt(2/5)
        float freq = (float)n * (CUDART_PI_F / CUTOFF_F);
        rbf_s[row][n - 1] = norm * sinf(d * freq) / d;  // full precision (one-time)
    }
    __syncthreads();

    float y[8];
    float b0 = b_rbf0[h];
    #pragma unroll
    for (int row = 0; row < 8; row++) y[row] = b0;
    #pragma unroll
    for (int r = 0; r < NRAD; r++) {
        float w = W_rbf0[r * HID + h];
        #pragma unroll
        for (int row = 0; row < 8; row++)
            y[row] = fmaf(rbf_s[row][r], w, y[row]);
    }
    #pragma unroll
    for (int row = 0; row < 8; row++) {
        float v = y[row];
        a_s[row][h] = v / (1.0f + expf(-v));           // accurate silu (one-time)
    }
    __syncthreads();

    float f[8];
    float bl = b_lin[h];                               // fold bias into LUT
    #pragma unroll
    for (int row = 0; row < 8; row++) f[row] = bl;
    for (int k = 0; k < HID; k++) {
        float w2 = W_lin[(size_t)(256 + k) * HID + h]; // W2 = rows 256..383
        #pragma unroll
        for (int row = 0; row < 8; row++)
            f[row] = fmaf(a_s[row][k], w2, f[row]);
    }

    float g[8];
    #pragma unroll
    for (int row = 0; row < 8; row++) g[row] = 0.0f;
    #pragma unroll
    for (int r = 0; r < NRAD; r++) {
        float w = W_rbf1[r * HID + h];
        #pragma unroll
        for (int row = 0; row < 8; row++)
            g[row] = fmaf(rbf_s[row][r], w, g[row]);
    }

    #pragma unroll
    for (int row = 0; row < 8; row++) {
        g_LUTh[(size_t)(r0 + row) * 256 + h]       = __float2half_rn(f[row]);
        g_LUTh[(size_t)(r0 + row) * 256 + 128 + h] = __float2half_rn(g[row]);
    }
}

// ---------------------------------------------------------------------------
// Kernel 3: edge kernel. CHANGE THIS ROUND: __stcs streaming stores so the
// 328 MB fp32 output stream doesn't write-allocate through L2 and evict the
// L2-resident Z (10.2 MB) + LUT (2.1 MB) working set.
//   e1 = silu(Z[src][0:128] + Z[dst][128:256] + lerp_f(d))   (b_lin pre-folded)
//   e2 = lerp_g(d) * e1
// ---------------------------------------------------------------------------
__device__ __forceinline__ float4 h4_to_f4(uint2 v) {
    __half2 lo = *reinterpret_cast<__half2*>(&v.x);
    __half2 hi = *reinterpret_cast<__half2*>(&v.y);
    float2 a = __half22float2(lo);
    float2 b = __half22float2(hi);
    return make_float4(a.x, a.y, b.x, b.y);
}

__global__ __launch_bounds__(256) void edge_kernel(
    const int*   __restrict__ ei,      // [2, E]
    const float* __restrict__ ew,      // [E]
    float*       __restrict__ out)     // [2*E*128]: e1 then e2
{
    const int warp = (blockIdx.x * blockDim.x + threadIdx.x) >> 5;
    const int lane = threadIdx.x & 31;
    if (warp >= N_EDGES) return;
    const int e = warp;

    const float d = __ldg(ew + e);
    const int   s = __ldg(ei + e);
    const int   t = __ldg(ei + N_EDGES + e);

    float tp = (d - D0) * LUT_INV;
    tp = fminf(fmaxf(tp, 0.0f), (float)(LUT_N - 1) - 1e-3f);  // clamp BEFORE cast
    int i0 = (int)tp;
    if (i0 > LUT_N - 2) i0 = LUT_N - 2;
    const float tw = tp - (float)i0;

    // LUT row = 256 halfs = 64 uint2; lane -> 4 hidden units (one uint2)
    const uint2* L0 = (const uint2*)(g_LUTh + (size_t)i0 * 256);
    const float4 f0 = h4_to_f4(__ldg(L0 + lane));
    const float4 g0 = h4_to_f4(__ldg(L0 + 32 + lane));
    const float4 f1 = h4_to_f4(__ldg(L0 + 64 + lane));   // next row, f part
    const float4 g1 = h4_to_f4(__ldg(L0 + 96 + lane));   // next row, g part

    const float4 zs = h4_to_f4(__ldg((const uint2*)(g_Zh + (size_t)s * 256) + lane));
    const float4 zd = h4_to_f4(__ldg((const uint2*)(g_Zh + (size_t)t * 256 + 128) + lane));

    float4 e1v, e2v;
    #define COMP(c)                                                    \
    {                                                                  \
        float fi  = fmaf(tw, f1.c - f0.c, f0.c);                       \
        float gi  = fmaf(tw, g1.c - g0.c, g0.c);                       \
        float pre = zs.c + zd.c + fi;                                  \
        float sv  = __fdividef(pre, 1.0f + __expf(-pre));              \
        e1v.c = sv;                                                    \
        e2v.c = gi * sv;                                               \
    }
    COMP(x) COMP(y) COMP(z) COMP(w)
    #undef COMP

    // Streaming stores: evict-first, keep Z/LUT resident in L2.
    __stcs((float4*)(out + (size_t)e * HID) + lane, e1v);
    __stcs((float4*)(out + (size_t)N_EDGES * HID + (size_t)e * HID) + lane, e2v);
}

// ---------------------------------------------------------------------------
extern "C" void kernel_launch(void* const* d_in, const int* in_sizes, int n_in,
                              void* d_out, int out_size)
{
    const float* node_embs = (const float*)d_in[0];
    const int*   edge_idx  = (const int*)  d_in[1];
    const float* edge_w    = (const float*)d_in[2];
    const float* W_rbf0    = (const float*)d_in[3];
    const float* b_rbf0    = (const float*)d_in[4];
    const float* W_lin     = (const float*)d_in[5];
    const float* b_lin     = (const float*)d_in[6];
    const float* W_rbf1    = (const float*)d_in[7];
    float* out = (float*)d_out;

    // 1) Z = node_embs @ [W0|W1], fp16 out. Single wave (grid 418 <= 444).
    {
        dim3 grid((N_NODES + 95) / 96, 2);
        z_gemm_kernel<<<grid, 256>>>(node_embs, W_lin);
    }
    // 2) d-dependent LUT (b_lin folded into f), fp16 out
    lut_kernel<<<LUT_N / 8, 128>>>(W_rbf0, b_rbf0, W_lin, b_lin, W_rbf1);
    // 3) per-edge fuse: warp per edge, 8 warps per block, streaming stores
    edge_kernel<<<(N_EDGES + 7) / 8, 256>>>(edge_idx, edge_w, out);

    (void)in_sizes; (void)n_in; (void)out_size;
}

// round 17
// speedup vs baseline: 1.8466x; 1.2925x over previous
#include <cuda_runtime.h>
#include <cuda_fp16.h>
#include <math_constants.h>

// Problem constants (fixed by the dataset)
#define N_NODES   20000
#define N_EDGES   320000
#define HID       128
#define NRAD      16
#define CUTOFF_F  5.0f
#define D0        0.5f
#define D1        5.0f

// LUT: f(d)=silu(rbf@W_rbf0+b0)@W2 + b_lin  and  g(d)=rbf@W_rbf1, lerp over d∈[0.5,5].
#define LUT_N     4096
#define LUT_STEP  ((D1 - D0) / (float)(LUT_N - 1))
#define LUT_INV   ((float)(LUT_N - 1) / (D1 - D0))

// fp16 scratch (validated: rel_err 2.8e-4 with exact GEMM)
__device__ __half g_Zh[N_NODES * 256];    // [node][0:128]=W0-proj, [128:256]=W1-proj (10.2 MB)
__device__ __half g_LUTh[LUT_N * 256];    // [row][0:128]=f(d)+b_lin, [128:256]=g(d)  (2.1 MB)

// ---------------------------------------------------------------------------
// Kernel 1: Z = node_embs @ [W0|W1] via HMMA mma.sync m16n8k16.
// SIMT fp32 version measured 40.4us = ~90% of the FFMA issue floor; tensor
// pipe was 0%. CTA = 128m x 128n (blockIdx.y = W block), K=128 in one pass.
// A tile + W block in fp16 smem; ldmatrix fragments; fp32 accumulate.
// 3 CTAs/SM (69.6KB dyn smem), grid 157x2=314 <= 444 slots: single wave.
// ---------------------------------------------------------------------------
__global__ __launch_bounds__(256, 3) void z_gemm_mma(
    const float* __restrict__ A,       // node_embs [20000,128]
    const float* __restrict__ W_lin)   // [384,128] row-major
{
    extern __shared__ __half smem[];
    __half* As = smem;                 // [128][136] (136-half pitch: ldmatrix conflict-free)
    __half* Ws = smem + 128 * 136;     // [128][136]

    const int m0   = blockIdx.x * 128;
    const int nblk = blockIdx.y;       // 0 -> W rows 0..127, 1 -> rows 128..255
    const int tid  = threadIdx.x;

    // Load W block (128x128 fp32 -> fp16), coalesced float2 reads.
    {
        const float2* Wsrc = (const float2*)(W_lin + (size_t)nblk * 128 * 128);
        for (int idx = tid; idx < 128 * 64; idx += 256) {
            int r = idx >> 6, c2 = idx & 63;
            float2 v = __ldg(Wsrc + r * 64 + c2);
            *(__half2*)&Ws[r * 136 + 2 * c2] = __floats2half2_rn(v.x, v.y);
        }
    }
    // Load A tile (zero-fill past N_NODES).
    {
        for (int idx = tid; idx < 128 * 64; idx += 256) {
            int r = idx >> 6, c2 = idx & 63;
            int gm = m0 + r;
            float2 v = make_float2(0.f, 0.f);
            if (gm < N_NODES) v = __ldg((const float2*)(A + (size_t)gm * 128) + c2);
            *(__half2*)&As[r * 136 + 2 * c2] = __floats2half2_rn(v.x, v.y);
        }
    }
    __syncthreads();

    const int w    = tid >> 5;         // warp = m-chunk (0..7)
    const int lane = tid & 31;
    const int g    = lane >> 2;        // 0..7
    const int t    = lane & 3;         // 0..3
    const int mbase = w * 16;

    // A fragments: 8 k-chunks x 4 regs, register-resident across the n loop.
    // ldmatrix.x4 tile order matches a0..a3: (rows0-7,k0-7)(rows8-15,k0-7)(rows0-7,k8-15)(rows8-15,k8-15)
    unsigned afrag[8][4];
    {
        unsigned arow = mbase + (lane & 15);
        #pragma unroll
        for (int kc = 0; kc < 8; kc++) {
            unsigned col = kc * 16 + (lane >> 4) * 8;
            unsigned addr = (unsigned)__cvta_generic_to_shared(&As[arow * 136 + col]);
            asm volatile("ldmatrix.sync.aligned.m8n8.x4.shared.b16 {%0,%1,%2,%3}, [%4];"
                : "=r"(afrag[kc][0]), "=r"(afrag[kc][1]),
                  "=r"(afrag[kc][2]), "=r"(afrag[kc][3])
                : "r"(addr));
        }
    }

    #pragma unroll 1
    for (int nc = 0; nc < 16; nc++) {
        const int n0 = nc * 8;
        // B fragments via trans-ldmatrix from k-major Ws: b0={B[2t][g],B[2t+1][g]}, b1=k+8.
        unsigned bfrag[8][2];
        #pragma unroll
        for (int kc = 0; kc < 8; kc++) {
            unsigned brow = kc * 16 + (lane & 15);
            unsigned addr = (unsigned)__cvta_generic_to_shared(&Ws[brow * 136 + n0]);
            asm volatile("ldmatrix.sync.aligned.m8n8.x2.trans.shared.b16 {%0,%1}, [%2];"
                : "=r"(bfrag[kc][0]), "=r"(bfrag[kc][1]) : "r"(addr));
        }
        float d0 = 0.f, d1 = 0.f, d2 = 0.f, d3 = 0.f;
        #pragma unroll
        for (int kc = 0; kc < 8; kc++) {
            asm volatile("mma.sync.aligned.m16n8k16.row.col.f32.f16.f16.f32 "
                "{%0,%1,%2,%3}, {%4,%5,%6,%7}, {%8,%9}, {%0,%1,%2,%3};"
                : "+f"(d0), "+f"(d1), "+f"(d2), "+f"(d3)
                : "r"(afrag[kc][0]), "r"(afrag[kc][1]),
                  "r"(afrag[kc][2]), "r"(afrag[kc][3]),
                  "r"(bfrag[kc][0]), "r"(bfrag[kc][1]));
        }
        // D layout: d0,d1 = (row g,  cols n0+2t, n0+2t+1); d2,d3 = (row g+8, same cols)
        const int col = nblk * 128 + n0 + 2 * t;
        const int gm0 = m0 + mbase + g;
        const int gm1 = gm0 + 8;
        if (gm0 < N_NODES)
            *(__half2*)&g_Zh[(size_t)gm0 * 256 + col] = __floats2half2_rn(d0, d1);
        if (gm1 < N_NODES)
            *(__half2*)&g_Zh[(size_t)gm1 * 256 + col] = __floats2half2_rn(d2, d3);
    }
}

#define ZGEMM_SMEM (2 * 128 * 136 * (int)sizeof(__half))   // 69632 B

// ---------------------------------------------------------------------------
// Kernel 2: LUT build (fp16 output). UNCHANGED.
// ---------------------------------------------------------------------------
__global__ __launch_bounds__(128) void lut_kernel(
    const float* __restrict__ W_rbf0,  // [16,128]
    const float* __restrict__ b_rbf0,  // [128]
    const float* __restrict__ W_lin,   // [384,128]
    const float* __restrict__ b_lin,   // [128]
    const float* __restrict__ W_rbf1)  // [16,128]
{
    __shared__ float rbf_s[8][NRAD];
    __shared__ float a_s[8][HID];

    const int h  = threadIdx.x;            // 0..127
    const int r0 = blockIdx.x * 8;

    {
        int row = h >> 4;
        int n   = (h & 15) + 1;
        float d = D0 + (float)(r0 + row) * LUT_STEP;
        const float norm = 0.6324555320336759f;        // sqrt(2/5)
        float freq = (float)n * (CUDART_PI_F / CUTOFF_F);
        rbf_s[row][n - 1] = norm * sinf(d * freq) / d;  // full precision (one-time)
    }
    __syncthreads();

    float y[8];
    float b0 = b_rbf0[h];
    #pragma unroll
    for (int row = 0; row < 8; row++) y[row] = b0;
    #pragma unroll
    for (int r = 0; r < NRAD; r++) {
        float w = W_rbf0[r * HID + h];
        #pragma unroll
        for (int row = 0; row < 8; row++)
            y[row] = fmaf(rbf_s[row][r], w, y[row]);
    }
    #pragma unroll
    for (int row = 0; row < 8; row++) {
        float v = y[row];
        a_s[row][h] = v / (1.0f + expf(-v));           // accurate silu (one-time)
    }
    __syncthreads();

    float f[8];
    float bl = b_lin[h];                               // fold bias into LUT
    #pragma unroll
    for (int row = 0; row < 8; row++) f[row] = bl;
    for (int k = 0; k < HID; k++) {
        float w2 = W_lin[(size_t)(256 + k) * HID + h]; // W2 = rows 256..383
        #pragma unroll
        for (int row = 0; row < 8; row++)
            f[row] = fmaf(a_s[row][k], w2, f[row]);
    }

    float g[8];
    #pragma unroll
    for (int row = 0; row < 8; row++) g[row] = 0.0f;
    #pragma unroll
    for (int r = 0; r < NRAD; r++) {
        float w = W_rbf1[r * HID + h];
        #pragma unroll
        for (int row = 0; row < 8; row++)
            g[row] = fmaf(rbf_s[row][r], w, g[row]);
    }

    #pragma unroll
    for (int row = 0; row < 8; row++) {
        g_LUTh[(size_t)(r0 + row) * 256 + h]       = __float2half_rn(f[row]);
        g_LUTh[(size_t)(r0 + row) * 256 + 128 + h] = __float2half_rn(g[row]);
    }
}

// ---------------------------------------------------------------------------
// Kernel 3: edge kernel. UNCHANGED from the 103.2us winner (__stcs stores).
// ---------------------------------------------------------------------------
__device__ __forceinline__ float4 h4_to_f4(uint2 v) {
    __half2 lo = *reinterpret_cast<__half2*>(&v.x);
    __half2 hi = *reinterpret_cast<__half2*>(&v.y);
    float2 a = __half22float2(lo);
    float2 b = __half22float2(hi);
    return make_float4(a.x, a.y, b.x, b.y);
}

__global__ __launch_bounds__(256) void edge_kernel(
    const int*   __restrict__ ei,      // [2, E]
    const float* __restrict__ ew,      // [E]
    float*       __restrict__ out)     // [2*E*128]: e1 then e2
{
    const int warp = (blockIdx.x * blockDim.x + threadIdx.x) >> 5;
    const int lane = threadIdx.x & 31;
    if (warp >= N_EDGES) return;
    const int e = warp;

    const float d = __ldg(ew + e);
    const int   s = __ldg(ei + e);
    const int   t = __ldg(ei + N_EDGES + e);

    float tp = (d - D0) * LUT_INV;
    tp = fminf(fmaxf(tp, 0.0f), (float)(LUT_N - 1) - 1e-3f);  // clamp BEFORE cast
    int i0 = (int)tp;
    if (i0 > LUT_N - 2) i0 = LUT_N - 2;
    const float tw = tp - (float)i0;

    // LUT row = 256 halfs = 64 uint2; lane -> 4 hidden units (one uint2)
    const uint2* L0 = (const uint2*)(g_LUTh + (size_t)i0 * 256);
    const float4 f0 = h4_to_f4(__ldg(L0 + lane));
    const float4 g0 = h4_to_f4(__ldg(L0 + 32 + lane));
    const float4 f1 = h4_to_f4(__ldg(L0 + 64 + lane));   // next row, f part
    const float4 g1 = h4_to_f4(__ldg(L0 + 96 + lane));   // next row, g part

    const float4 zs = h4_to_f4(__ldg((const uint2*)(g_Zh + (size_t)s * 256) + lane));
    const float4 zd = h4_to_f4(__ldg((const uint2*)(g_Zh + (size_t)t * 256 + 128) + lane));

    float4 e1v, e2v;
    #define COMP(c)                                                    \
    {                                                                  \
        float fi  = fmaf(tw, f1.c - f0.c, f0.c);                       \
        float gi  = fmaf(tw, g1.c - g0.c, g0.c);                       \
        float pre = zs.c + zd.c + fi;                                  \
        float sv  = __fdividef(pre, 1.0f + __expf(-pre));              \
        e1v.c = sv;                                                    \
        e2v.c = gi * sv;                                               \
    }
    COMP(x) COMP(y) COMP(z) COMP(w)
    #undef COMP

    // Streaming stores: evict-first, keep Z/LUT resident in L2.
    __stcs((float4*)(out + (size_t)e * HID) + lane, e1v);
    __stcs((float4*)(out + (size_t)N_EDGES * HID + (size_t)e * HID) + lane, e2v);
}

// ---------------------------------------------------------------------------
extern "C" void kernel_launch(void* const* d_in, const int* in_sizes, int n_in,
                              void* d_out, int out_size)
{
    const float* node_embs = (const float*)d_in[0];
    const int*   edge_idx  = (const int*)  d_in[1];
    const float* edge_w    = (const float*)d_in[2];
    const float* W_rbf0    = (const float*)d_in[3];
    const float* b_rbf0    = (const float*)d_in[4];
    const float* W_lin     = (const float*)d_in[5];
    const float* b_lin     = (const float*)d_in[6];
    const float* W_rbf1    = (const float*)d_in[7];
    float* out = (float*)d_out;

    // Opt-in to 69.6KB dynamic smem (deterministic, not a stream op, no alloc).
    cudaFuncSetAttribute(z_gemm_mma, cudaFuncAttributeMaxDynamicSharedMemorySize,
                         ZGEMM_SMEM);

    // 1) Z = node_embs @ [W0|W1] via tensor cores, fp16 out. Single wave.
    {
        dim3 grid((N_NODES + 127) / 128, 2);
        z_gemm_mma<<<grid, 256, ZGEMM_SMEM>>>(node_embs, W_lin);
    }
    // 2) d-dependent LUT (b_lin folded into f), fp16 out
    lut_kernel<<<LUT_N / 8, 128>>>(W_rbf0, b_rbf0, W_lin, b_lin, W_rbf1);
    // 3) per-edge fuse: warp per edge, 8 warps per block, streaming stores
    edge_kernel<<<(N_EDGES + 7) / 8, 256>>>(edge_idx, edge_w, out);

    (void)in_sizes; (void)n_in; (void)out_size;
}